// round 8
// baseline (speedup 1.0000x reference)
#include <cuda_runtime.h>
#include <cstdint>

#define NB 8
#define NN 2048
#define HH 512
#define MROWS (NB * NN)   // 16384

// ---------------------------------------------------------------------------
// Scratch (device globals — no allocation allowed)
// ---------------------------------------------------------------------------
__device__ float g_x[MROWS * HH];                 // residual x (fp32)
__device__ float g_xr[MROWS * HH];                // tf32-rounded copy of x
__device__ float g_h[MROWS * 1024];               // layer activations (fp32)
__device__ float g_hr[MROWS * 1024];              // tf32-rounded copy of h
__device__ float g_hwt[1024 * MROWS];             // (h @ W)^T [Fo][MROWS], tf32
__device__ float g_P[(size_t)MROWS * NN];         // unnormalized attention (tf32)
__device__ float g_wt[1024 * 1024];               // W^T [N][K], tf32
__device__ uint32_t g_adjT[MROWS * (NN / 32)];    // bit: valid(t, s), self-loop folded
__device__ float g_esrc[MROWS], g_edst[MROWS];
__device__ float g_f1[MROWS], g_f2[MROWS];        // per-source exp factors
__device__ float g_qa[MROWS], g_qb[MROWS];        // per-target exp factors
__device__ float g_rz[MROWS];                     // 1 / row-sum of P'
__device__ unsigned int g_smax_bits[NB];          // orderable-int max of esrc per batch
__device__ float g_Weff[6 * HH];
__device__ float g_beff[HH];

// ---------------------------------------------------------------------------
// Helpers
// ---------------------------------------------------------------------------
__device__ __forceinline__ float cvt_tf32f(float x) {
    uint32_t r;
    asm("cvt.rna.tf32.f32 %0, %1;" : "=r"(r) : "f"(x));
    return __uint_as_float(r);
}
__device__ __forceinline__ unsigned enc_ord(float f) {
    unsigned i = __float_as_uint(f);
    return (i & 0x80000000u) ? ~i : (i | 0x80000000u);
}
__device__ __forceinline__ float dec_ord(unsigned k) {
    unsigned i = (k & 0x80000000u) ? (k & 0x7FFFFFFFu) : ~k;
    return __uint_as_float(i);
}
__device__ __forceinline__ uint32_t smem_u32(const void* p) {
    uint32_t a;
    asm("{ .reg .u64 t; cvta.to.shared.u64 t, %1; cvt.u32.u64 %0, t; }" : "=r"(a) : "l"(p));
    return a;
}
__device__ __forceinline__ void mma8u(float* c, const uint32_t* a, uint32_t b0, uint32_t b1) {
    asm volatile(
        "mma.sync.aligned.m16n8k8.row.col.f32.tf32.tf32.f32 "
        "{%0,%1,%2,%3}, {%4,%5,%6,%7}, {%8,%9}, {%0,%1,%2,%3};"
        : "+f"(c[0]), "+f"(c[1]), "+f"(c[2]), "+f"(c[3])
        : "r"(a[0]), "r"(a[1]), "r"(a[2]), "r"(a[3]), "r"(b0), "r"(b1));
}
__device__ __forceinline__ void ldsm4(uint32_t* r, uint32_t addr) {
    asm volatile("ldmatrix.sync.aligned.m8n8.x4.shared.b16 {%0,%1,%2,%3}, [%4];"
                 : "=r"(r[0]), "=r"(r[1]), "=r"(r[2]), "=r"(r[3]) : "r"(addr));
}
#define CPA(dst, src) asm volatile("cp.async.cg.shared.global [%0], [%1], 16;" :: "r"(dst), "l"(src))
#define CPC() asm volatile("cp.async.commit_group;")
#define CPW(n) asm volatile("cp.async.wait_group %0;" :: "n"(n))

// k-major swizzled tile: row (m or n), 32 floats (8 float4) per row.
// float offset of float4 (row, c4): row*32 + ((c4 ^ (row&7)) << 2)
#define SOFF(row, c4) ((row) * 32 + (((c4) ^ ((row) & 7)) << 2))

// Tile: M=128, N=256. Stage = A 16KB + B 32KB = 48KB; 3 stages.
#define STAGE_BYTES 49152
#define A_BYTES 16384
#define SMEM_BYTES (3 * STAGE_BYTES)   // 147456

// ---------------------------------------------------------------------------
// Unified tf32 tensor-core GEMM, all operands pre-tf32-rounded in gmem.
// C[M,N] = A[M,K] @ Bt^T.  A row-major [M][K], Bt [N][K], both k-contiguous.
// CTA tile 128x256, 8 warps (2m x 4n), warp tile 64x64.
// EPI 0: Ct[n][m] = cvt_tf32(acc)                  (transposed store -> hwt)
// EPI 1: C = relu(acc*rz + bias); Cr = cvt(C)      (attention mid, batched)
// EPI 2: C = acc*rz + bias + X;   Cr = cvt(C)      (attention last, batched)
// EPI 3: C = X + relu(acc + bias); Cr = cvt(C)     (ff1)
// EPI 4: C = (X + relu(acc + bias)) * act[row]     (ff2, final output)
// ---------------------------------------------------------------------------
template <int EPI>
__global__ __launch_bounds__(256, 1) void gemm_tc(
    const float* __restrict__ A, const float* __restrict__ Bt,
    float* __restrict__ C, float* __restrict__ Cr, int K, int N,
    const float* __restrict__ bias, const float* __restrict__ X,
    const float* __restrict__ act, const float* __restrict__ rz)
{
    constexpr bool BATCHED = (EPI == 1 || EPI == 2);
    extern __shared__ float smf[];
    const uint32_t sbase = smem_u32(smf);
    const int tid = threadIdx.x;
    const int lane = tid & 31, wid = tid >> 5;

    // CTA rasterization swizzle: groups of 4 m-rows x full n share L2
    int bx = blockIdx.x, by = blockIdx.y;
    {
        const int GX = gridDim.x;
        const int lin = by * GX + bx;
        const int grp = lin / (4 * GX);
        const int rem = lin - grp * 4 * GX;
        by = grp * 4 + (rem & 3);
        bx = rem >> 2;
    }
    const int m0 = by * 128, n0 = bx * 256;
    const int ws = wid >> 2, wcs = wid & 3;
    const int wm = ws * 64, wn = wcs * 64;

    int zoff = 0;
    if (BATCHED) zoff = blockIdx.z * NN;
    const float* Ab = A + (size_t)zoff * K;
    const int ldb = BATCHED ? MROWS : K;
    const int kboff = BATCHED ? zoff : 0;
    float* Cb = C + (size_t)zoff * N;
    float* Crb = (Cr != nullptr) ? Cr + (size_t)zoff * N : nullptr;
    const float* Xb = (EPI >= 2) ? X + (size_t)zoff * N : nullptr;
    const float* rzb = BATCHED ? rz + zoff : nullptr;

    float acc[4][8][4];
#pragma unroll
    for (int i = 0; i < 4; i++)
#pragma unroll
        for (int j = 0; j < 8; j++)
#pragma unroll
            for (int q = 0; q < 4; q++) acc[i][j][q] = 0.f;

    const int row_l = tid >> 3, c4_l = tid & 7;

    auto issue = [&](int kt) {
        const int k0 = kt << 5;
        const uint32_t aB = sbase + (kt % 3) * STAGE_BYTES;
        const uint32_t bB = aB + A_BYTES;
#pragma unroll
        for (int p = 0; p < 4; p++) {
            const int row = row_l + p * 32;
            CPA(aB + SOFF(row, c4_l) * 4, Ab + (size_t)(m0 + row) * K + k0 + c4_l * 4);
        }
#pragma unroll
        for (int p = 0; p < 8; p++) {
            const int row = row_l + p * 32;
            CPA(bB + SOFF(row, c4_l) * 4,
                Bt + (size_t)(n0 + row) * ldb + kboff + k0 + c4_l * 4);
        }
        CPC();
    };

    auto compute = [&](int stg) {
        const uint32_t aB = sbase + stg * STAGE_BYTES;
        const uint32_t bB = aB + A_BYTES;
        const int mA = lane & 15, cA = lane >> 4;
        const int nB = (lane & 7) + ((lane >> 4) << 3), cB = (lane >> 3) & 1;
#pragma unroll
        for (int kk = 0; kk < 4; kk++) {
            uint32_t fa[4][4], fb[4][4];
#pragma unroll
            for (int mf = 0; mf < 4; mf++) {
                const int m = wm + mf * 16 + mA;
                ldsm4(fa[mf], aB + SOFF(m, kk * 2 + cA) * 4);
            }
#pragma unroll
            for (int j = 0; j < 4; j++) {
                const int n = wn + j * 16 + nB;
                ldsm4(fb[j], bB + SOFF(n, kk * 2 + cB) * 4);
            }
#pragma unroll
            for (int mf = 0; mf < 4; mf++)
#pragma unroll
                for (int nf = 0; nf < 8; nf++)
                    mma8u(acc[mf][nf], fa[mf], fb[nf >> 1][(nf & 1) * 2],
                          fb[nf >> 1][(nf & 1) * 2 + 1]);
        }
    };

    const int nkt = K >> 5;
    issue(0);
    issue(1);
    for (int kt = 0; kt < nkt; kt++) {
        if (kt < nkt - 1) { CPW(1); } else { CPW(0); }
        __syncthreads();
        if (kt + 2 < nkt) issue(kt + 2);
        compute(kt % 3);
    }

    // ---- epilogue ----
#pragma unroll
    for (int mf = 0; mf < 4; mf++) {
#pragma unroll
        for (int rr = 0; rr < 2; rr++) {
            const int r = m0 + wm + mf * 16 + (lane >> 2) + rr * 8;
            float rzv = 1.f, actv = 1.f;
            if (BATCHED) rzv = rzb[r];
            if (EPI == 4) actv = act[r];
#pragma unroll
            for (int nf = 0; nf < 8; nf++) {
                const int cc = n0 + wn + nf * 8 + (lane & 3) * 2;
                float v0 = acc[mf][nf][rr * 2 + 0];
                float v1 = acc[mf][nf][rr * 2 + 1];
                if (EPI == 0) {
                    C[(size_t)cc * MROWS + r]       = cvt_tf32f(v0);
                    C[(size_t)(cc + 1) * MROWS + r] = cvt_tf32f(v1);
                } else {
                    if (BATCHED) { v0 *= rzv; v1 *= rzv; }
                    v0 += bias[cc]; v1 += bias[cc + 1];
                    if (EPI == 1) { v0 = fmaxf(v0, 0.f); v1 = fmaxf(v1, 0.f); }
                    else if (EPI == 2) {
                        const float* xr = Xb + (size_t)r * N + cc;
                        v0 += xr[0]; v1 += xr[1];
                    } else if (EPI == 3) {
                        const float* xr = Xb + (size_t)r * N + cc;
                        v0 = xr[0] + fmaxf(v0, 0.f); v1 = xr[1] + fmaxf(v1, 0.f);
                    } else if (EPI == 4) {
                        const float* xr = Xb + (size_t)r * N + cc;
                        v0 = (xr[0] + fmaxf(v0, 0.f)) * actv;
                        v1 = (xr[1] + fmaxf(v1, 0.f)) * actv;
                    }
                    *reinterpret_cast<float2*>(Cb + (size_t)r * N + cc) = make_float2(v0, v1);
                    if (EPI == 1 || EPI == 2 || EPI == 3) {
                        *reinterpret_cast<float2*>(Crb + (size_t)r * N + cc) =
                            make_float2(cvt_tf32f(v0), cvt_tf32f(v1));
                    }
                }
            }
        }
    }
}

// ---------------------------------------------------------------------------
// 32x32 tiled transpose with tf32 rounding: out[C][R] = cvt(in[R][C]^T)
// ---------------------------------------------------------------------------
__global__ void transpose_kernel(const float* __restrict__ in, float* __restrict__ out,
                                 int R, int Cc)
{
    __shared__ float tile[32][33];
    int c0 = blockIdx.x * 32, r0 = blockIdx.y * 32;
    int x = threadIdx.x, y = threadIdx.y;
#pragma unroll
    for (int i = 0; i < 32; i += 8)
        tile[y + i][x] = in[(size_t)(r0 + y + i) * Cc + c0 + x];
    __syncthreads();
#pragma unroll
    for (int i = 0; i < 32; i += 8)
        out[(size_t)(c0 + y + i) * R + r0 + x] = cvt_tf32f(tile[x][y + i]);
}

// ---------------------------------------------------------------------------
// adjT: bit s of word (b,t,s/32) = (adj[b][s][t]!=0) | (s==t)
// ---------------------------------------------------------------------------
__global__ __launch_bounds__(1024) void adjT_kernel(const int* __restrict__ adj)
{
    __shared__ int sa[32][33];
    const int b = blockIdx.z, t0 = blockIdx.y * 32, s0 = blockIdx.x * 32;
    const int w = threadIdx.x >> 5, lane = threadIdx.x & 31;
    sa[w][lane] = adj[((size_t)b * NN + s0 + w) * NN + t0 + lane];
    __syncthreads();
    const int t = t0 + w;
    uint32_t word = __ballot_sync(0xFFFFFFFFu, sa[lane][w] != 0);
    if (lane == 0) {
        if ((t >> 5) == (s0 >> 5)) word |= 1u << (t & 31);
        g_adjT[((size_t)b * NN + t) * (NN / 32) + (s0 >> 5)] = word;
    }
}

// ---------------------------------------------------------------------------
// Weff = emb_W1 @ emb_W2 ; beff = emb_b1 @ emb_W2 + emb_b2
// ---------------------------------------------------------------------------
__global__ void prep_weff_kernel(const float* __restrict__ W1, const float* __restrict__ b1,
                                 const float* __restrict__ W2, const float* __restrict__ b2)
{
    int j = blockIdx.x * 256 + threadIdx.x;
    if (j >= HH) return;
    float acc[6] = {0.f, 0.f, 0.f, 0.f, 0.f, 0.f};
    float bacc = b2[j];
    for (int k = 0; k < HH; k++) {
        float w2 = W2[k * HH + j];
        bacc += b1[k] * w2;
#pragma unroll
        for (int i = 0; i < 6; i++) acc[i] += W1[i * HH + k] * w2;
    }
#pragma unroll
    for (int i = 0; i < 6; i++) g_Weff[i * HH + j] = acc[i];
    g_beff[j] = bacc;
}

// ---------------------------------------------------------------------------
// Feature construction + fused 6->512 embedding; writes x and xr = tf32(x)
// ---------------------------------------------------------------------------
__global__ void embed_kernel(const float* __restrict__ arr, const float* __restrict__ dep,
                             const float* __restrict__ hard,
                             const float* __restrict__ ts, const float* __restrict__ tt)
{
    int idx = blockIdx.x * 256 + threadIdx.x;
    int j = idx & (HH - 1);
    int row = idx >> 9;
    int b = row >> 11;
    float t = ts[b], T = tt[b];
    float ar = arr[row], de = dep[row];
    float f[6];
    f[0] = (t - ar) / (de - ar);
    f[1] = t / T;
    f[2] = fmodf(f[1], 2.f);
    f[3] = fmodf(f[1], 4.f);
    f[4] = fmodf(f[1], 7.f);
    f[5] = hard[row];
    float acc = g_beff[j];
#pragma unroll
    for (int i = 0; i < 6; i++) acc += f[i] * g_Weff[i * HH + j];
    g_x[idx] = acc;
    g_xr[idx] = cvt_tf32f(acc);
}

// ---------------------------------------------------------------------------
// e_src / e_dst from hwt (coalesced columns) + per-batch max via atomicMax
// ---------------------------------------------------------------------------
__global__ void reset_smax_kernel()
{
    if (threadIdx.x < NB) g_smax_bits[threadIdx.x] = 0x007FFFFFu;  // enc(-inf)
}

__global__ __launch_bounds__(256) void e2_kernel(const float* __restrict__ asrc,
                                                 const float* __restrict__ adst, int Fo)
{
    __shared__ float sa[1024], sd[1024];
    const int tid = threadIdx.x;
    for (int f = tid; f < Fo; f += 256) { sa[f] = asrc[f]; sd[f] = adst[f]; }
    __syncthreads();
    const int r = blockIdx.x * 256 + tid;
    const float* col = g_hwt + r;
    float ps = 0.f, pd = 0.f;
    for (int f = 0; f < Fo; f += 4) {
        float v0 = col[(size_t)(f + 0) * MROWS];
        float v1 = col[(size_t)(f + 1) * MROWS];
        float v2 = col[(size_t)(f + 2) * MROWS];
        float v3 = col[(size_t)(f + 3) * MROWS];
        ps += v0 * sa[f] + v1 * sa[f + 1] + v2 * sa[f + 2] + v3 * sa[f + 3];
        pd += v0 * sd[f] + v1 * sd[f + 1] + v2 * sd[f + 2] + v3 * sd[f + 3];
    }
    g_esrc[r] = ps;
    g_edst[r] = pd;
    __shared__ float red[256];
    red[tid] = ps;
    __syncthreads();
    for (int s = 128; s; s >>= 1) {
        if (tid < s) red[tid] = fmaxf(red[tid], red[tid + s]);
        __syncthreads();
    }
    if (tid == 0) atomicMax(&g_smax_bits[r >> 11], enc_ord(red[0]));
}

// ---------------------------------------------------------------------------
// Per-node exp factors (all exponents <= 0 -> no overflow)
// ---------------------------------------------------------------------------
__global__ void nodeprep_kernel()
{
    int t = blockIdx.x * 256 + threadIdx.x;
    int b = t >> 11;
    float sm = dec_ord(g_smax_bits[b]);
    float es = g_esrc[t], ed = g_edst[t];
    g_f1[t] = __expf(es - sm);
    g_f2[t] = __expf(0.2f * (es - sm));
    float u = ed + sm;
    float mh = fmaxf(u, 0.2f * u);
    g_qa[t] = __expf(u - mh);
    g_qb[t] = __expf(0.2f * u - mh);
}

// ---------------------------------------------------------------------------
// Materialize P' (tf32-rounded) + fused row-sum -> g_rz. One warp per row.
// ---------------------------------------------------------------------------
__global__ __launch_bounds__(256) void pgen_kernel()
{
    const int wid = threadIdx.x >> 5, lane = threadIdx.x & 31;
    const int t = blockIdx.x * 8 + wid;
    const int b = t >> 11;
    const float qa = g_qa[t], qb = g_qb[t];
    const uint32_t* wrow = g_adjT + (size_t)t * (NN / 32);
    const float* f1 = g_f1 + b * NN;
    const float* f2 = g_f2 + b * NN;
    float* Prow = g_P + (size_t)t * NN;
    float sum = 0.f;
#pragma unroll 4
    for (int i = 0; i < 16; i++) {
        const int s = i * 128 + lane * 4;
        const uint32_t w = wrow[s >> 5];
        const uint32_t sh = s & 31;
        float4 x1 = *reinterpret_cast<const float4*>(f1 + s);
        float4 x2 = *reinterpret_cast<const float4*>(f2 + s);
        float4 o;
        o.x = ((w >> (sh + 0)) & 1u) ? cvt_tf32f(fmaxf(qa * x1.x, qb * x2.x)) : 0.f;
        o.y = ((w >> (sh + 1)) & 1u) ? cvt_tf32f(fmaxf(qa * x1.y, qb * x2.y)) : 0.f;
        o.z = ((w >> (sh + 2)) & 1u) ? cvt_tf32f(fmaxf(qa * x1.z, qb * x2.z)) : 0.f;
        o.w = ((w >> (sh + 3)) & 1u) ? cvt_tf32f(fmaxf(qa * x1.w, qb * x2.w)) : 0.f;
        sum += (o.x + o.y) + (o.z + o.w);
        *reinterpret_cast<float4*>(Prow + s) = o;
    }
#pragma unroll
    for (int off = 16; off; off >>= 1) sum += __shfl_xor_sync(0xFFFFFFFFu, sum, off);
    if (lane == 0) g_rz[t] = 1.f / fmaxf(sum, 1e-30f);
}

// ---------------------------------------------------------------------------
// Host launcher
// ---------------------------------------------------------------------------
extern "C" void kernel_launch(void* const* d_in, const int* in_sizes, int n_in,
                              void* d_out, int out_size)
{
    const int*   adj      = (const int*)d_in[0];
    const float* arrivals = (const float*)d_in[1];
    const float* depart   = (const float*)d_in[2];
    const float* hard     = (const float*)d_in[3];
    const float* active   = (const float*)d_in[4];
    const float* timestep = (const float*)d_in[5];
    const float* totalts  = (const float*)d_in[6];
    const float* embW1 = (const float*)d_in[7];
    const float* embb1 = (const float*)d_in[8];
    const float* embW2 = (const float*)d_in[9];
    const float* embb2 = (const float*)d_in[10];
    const float* gatW[3]    = {(const float*)d_in[11], (const float*)d_in[15], (const float*)d_in[19]};
    const float* gatAsrc[3] = {(const float*)d_in[12], (const float*)d_in[16], (const float*)d_in[20]};
    const float* gatAdst[3] = {(const float*)d_in[13], (const float*)d_in[17], (const float*)d_in[21]};
    const float* gatB[3]    = {(const float*)d_in[14], (const float*)d_in[18], (const float*)d_in[22]};
    const float* ffW1 = (const float*)d_in[23];
    const float* ffb1 = (const float*)d_in[24];
    const float* ffW2 = (const float*)d_in[25];
    const float* ffb2 = (const float*)d_in[26];

    float *x, *xr, *h, *hr, *hwt, *P, *rz, *wt;
    cudaGetSymbolAddress((void**)&x,   g_x);
    cudaGetSymbolAddress((void**)&xr,  g_xr);
    cudaGetSymbolAddress((void**)&h,   g_h);
    cudaGetSymbolAddress((void**)&hr,  g_hr);
    cudaGetSymbolAddress((void**)&hwt, g_hwt);
    cudaGetSymbolAddress((void**)&P,   g_P);
    cudaGetSymbolAddress((void**)&rz,  g_rz);
    cudaGetSymbolAddress((void**)&wt,  g_wt);

    static int smem_set = 0;
    if (!smem_set) {
        cudaFuncSetAttribute(gemm_tc<0>, cudaFuncAttributeMaxDynamicSharedMemorySize, SMEM_BYTES);
        cudaFuncSetAttribute(gemm_tc<1>, cudaFuncAttributeMaxDynamicSharedMemorySize, SMEM_BYTES);
        cudaFuncSetAttribute(gemm_tc<2>, cudaFuncAttributeMaxDynamicSharedMemorySize, SMEM_BYTES);
        cudaFuncSetAttribute(gemm_tc<3>, cudaFuncAttributeMaxDynamicSharedMemorySize, SMEM_BYTES);
        cudaFuncSetAttribute(gemm_tc<4>, cudaFuncAttributeMaxDynamicSharedMemorySize, SMEM_BYTES);
        smem_set = 1;
    }

    prep_weff_kernel<<<2, 256>>>(embW1, embb1, embW2, embb2);
    embed_kernel<<<(MROWS * HH) / 256, 256>>>(arrivals, depart, hard, timestep, totalts);
    adjT_kernel<<<dim3(NN / 32, NN / 32, NB), 1024>>>(adj);

    const int Kin[3] = {HH, 1024, 1024};
    const int Fo[3]  = {1024, 1024, HH};
    const dim3 tblk(32, 8);

    for (int l = 0; l < 3; l++) {
        const float* Ain = (l == 0) ? xr : hr;   // pre-rounded activations
        // wt = tf32(W^T) [Fo][Kin]
        transpose_kernel<<<dim3(Fo[l] / 32, Kin[l] / 32), tblk>>>(gatW[l], wt, Kin[l], Fo[l]);
        // hwt = (hin @ W)^T  (written transposed, tf32-rounded)
        gemm_tc<0><<<dim3(Fo[l] / 256, MROWS / 128), 256, SMEM_BYTES>>>(
            Ain, wt, hwt, nullptr, Kin[l], Fo[l], nullptr, nullptr, nullptr, nullptr);
        reset_smax_kernel<<<1, 32>>>();
        e2_kernel<<<MROWS / 256, 256>>>(gatAsrc[l], gatAdst[l], Fo[l]);
        nodeprep_kernel<<<MROWS / 256, 256>>>();
        pgen_kernel<<<MROWS / 8, 256>>>();
        if (l < 2) {
            gemm_tc<1><<<dim3(Fo[l] / 256, NN / 128, NB), 256, SMEM_BYTES>>>(
                P, hwt, h, hr, NN, Fo[l], gatB[l], nullptr, nullptr, rz);
        } else {
            gemm_tc<2><<<dim3(Fo[l] / 256, NN / 128, NB), 256, SMEM_BYTES>>>(
                P, hwt, h, hr, NN, Fo[l], gatB[l], x, nullptr, rz);
        }
    }

    // ff1: x2 = x1 + relu(x1 @ W1 + b1)   (A = hr pre-rounded, X = h fp32)
    transpose_kernel<<<dim3(HH / 32, HH / 32), tblk>>>(ffW1, wt, HH, HH);
    gemm_tc<3><<<dim3(HH / 256, MROWS / 128), 256, SMEM_BYTES>>>(
        hr, wt, x, xr, HH, HH, ffb1, h, nullptr, nullptr);
    // ff2: out = (x2 + relu(x2 @ W2 + b2)) * active   (A = xr)
    transpose_kernel<<<dim3(HH / 32, HH / 32), tblk>>>(ffW2, wt, HH, HH);
    gemm_tc<4><<<dim3(HH / 256, MROWS / 128), 256, SMEM_BYTES>>>(
        xr, wt, (float*)d_out, nullptr, HH, HH, ffb2, x, active, nullptr);
}

// round 9
// speedup vs baseline: 1.2470x; 1.2470x over previous
#include <cuda_runtime.h>
#include <cstdint>

#define NB 8
#define NN 2048
#define HH 512
#define MROWS (NB * NN)   // 16384

// ---------------------------------------------------------------------------
// Scratch (device globals — no allocation allowed)
// ---------------------------------------------------------------------------
__device__ float g_x[MROWS * HH];                 // residual x (fp32)
__device__ float g_xr[MROWS * HH];                // tf32-rounded copy of x
__device__ float g_h[MROWS * 1024];               // layer activations (fp32, layer-2 only)
__device__ float g_hr[MROWS * 1024];              // tf32-rounded activations
__device__ float g_hwt[1024 * MROWS];             // (h @ W)^T [Fo][MROWS], tf32
__device__ float g_P[(size_t)MROWS * NN];         // unnormalized attention (tf32)
__device__ float g_wt[1024 * 1024];               // W^T [N][K], tf32
__device__ uint32_t g_adjT[MROWS * (NN / 32)];    // bit: valid(t, s), self-loop folded
__device__ float g_ee[2 * MROWS];                 // [0..M) esrc, [M..2M) edst
__device__ float g_f1[MROWS], g_f2[MROWS];        // per-source exp factors
__device__ float g_qa[MROWS], g_qb[MROWS];        // per-target exp factors
__device__ float g_rz[MROWS];                     // 1 / row-sum of P'
__device__ unsigned int g_smax_bits[NB];          // orderable-int max of esrc per batch
__device__ float g_Weff[6 * HH];
__device__ float g_beff[HH];

// ---------------------------------------------------------------------------
// Helpers
// ---------------------------------------------------------------------------
__device__ __forceinline__ float cvt_tf32f(float x) {
    uint32_t r;
    asm("cvt.rna.tf32.f32 %0, %1;" : "=r"(r) : "f"(x));
    return __uint_as_float(r);
}
__device__ __forceinline__ unsigned enc_ord(float f) {
    unsigned i = __float_as_uint(f);
    return (i & 0x80000000u) ? ~i : (i | 0x80000000u);
}
__device__ __forceinline__ float dec_ord(unsigned k) {
    unsigned i = (k & 0x80000000u) ? (k & 0x7FFFFFFFu) : ~k;
    return __uint_as_float(i);
}
__device__ __forceinline__ uint32_t smem_u32(const void* p) {
    uint32_t a;
    asm("{ .reg .u64 t; cvta.to.shared.u64 t, %1; cvt.u32.u64 %0, t; }" : "=r"(a) : "l"(p));
    return a;
}
__device__ __forceinline__ void mma8u(float* c, const uint32_t* a, uint32_t b0, uint32_t b1) {
    asm volatile(
        "mma.sync.aligned.m16n8k8.row.col.f32.tf32.tf32.f32 "
        "{%0,%1,%2,%3}, {%4,%5,%6,%7}, {%8,%9}, {%0,%1,%2,%3};"
        : "+f"(c[0]), "+f"(c[1]), "+f"(c[2]), "+f"(c[3])
        : "r"(a[0]), "r"(a[1]), "r"(a[2]), "r"(a[3]), "r"(b0), "r"(b1));
}
__device__ __forceinline__ void ldsm4(uint32_t* r, uint32_t addr) {
    asm volatile("ldmatrix.sync.aligned.m8n8.x4.shared.b16 {%0,%1,%2,%3}, [%4];"
                 : "=r"(r[0]), "=r"(r[1]), "=r"(r[2]), "=r"(r[3]) : "r"(addr));
}
#define CPA(dst, src) asm volatile("cp.async.cg.shared.global [%0], [%1], 16;" :: "r"(dst), "l"(src))
#define CPC() asm volatile("cp.async.commit_group;")
#define CPW(n) asm volatile("cp.async.wait_group %0;" :: "n"(n))

// k-major swizzled tile: row (m or n) = 0..127, 32 floats (8 float4) per row.
#define SOFF(row, c4) ((row) * 32 + (((c4) ^ ((row) & 7)) << 2))

#define STAGE_BYTES 32768                 // A 16KB + B 16KB per stage
#define SMEM_BYTES (3 * STAGE_BYTES)      // 3-stage cp.async pipeline, 96 KB

// ---------------------------------------------------------------------------
// Unified tf32 tensor-core GEMM, all operands pre-tf32-rounded in gmem.
// C[M,N] = A[M,K] @ Bt^T.  A row-major [M][K], Bt [N][K], both k-contiguous.
// CTA tile 128x128, 8 warps (2m x 4n), warp tile 64x32, 2 CTAs/SM.
// EPI 0: Ct[n][m] = cvt(acc); fused esrc/edst partial dots (bias=asrc, X=adst,
//        Cr = g_ee base) via shfl-reduce + atomicAdd
// EPI 1: C = cvt(relu(acc*rz + bias))              (attention mid; tf32 only)
// EPI 2: C = acc*rz + bias + X; Cr = cvt(C)        (attention last, batched)
// EPI 3: C = X + relu(acc + bias); Cr = cvt(C)     (ff1)
// EPI 4: C = (X + relu(acc + bias)) * act[row]     (ff2, final output)
// ---------------------------------------------------------------------------
template <int EPI>
__global__ __launch_bounds__(256, 2) void gemm_tc(
    const float* __restrict__ A, const float* __restrict__ Bt,
    float* __restrict__ C, float* __restrict__ Cr, int K, int N,
    const float* __restrict__ bias, const float* __restrict__ X,
    const float* __restrict__ act, const float* __restrict__ rz)
{
    constexpr bool BATCHED = (EPI == 1 || EPI == 2);
    extern __shared__ float smf[];
    const uint32_t sbase = smem_u32(smf);
    const int tid = threadIdx.x;
    const int lane = tid & 31, wid = tid >> 5;

    // CTA rasterization swizzle: groups of 4 m-rows x full n share L2
    int bx = blockIdx.x, by = blockIdx.y;
    {
        const int GX = gridDim.x;
        const int lin = by * GX + bx;
        const int grp = lin / (4 * GX);
        const int rem = lin - grp * 4 * GX;
        by = grp * 4 + (rem & 3);
        bx = rem >> 2;
    }
    const int m0 = by * 128, n0 = bx * 128;
    const int ws = wid >> 2, wcs = wid & 3;
    const int wm = ws * 64, wn = wcs * 32;

    int zoff = 0;
    if (BATCHED) zoff = blockIdx.z * NN;
    const float* Ab = A + (size_t)zoff * K;
    const int ldb = BATCHED ? MROWS : K;
    const int kboff = BATCHED ? zoff : 0;
    float* Cb = C + (size_t)zoff * N;
    float* Crb = (Cr != nullptr) ? Cr + (size_t)zoff * N : nullptr;
    const float* Xb = (EPI >= 2) ? X + (size_t)zoff * N : nullptr;
    const float* rzb = BATCHED ? rz + zoff : nullptr;

    float acc[4][4][4];
#pragma unroll
    for (int i = 0; i < 4; i++)
#pragma unroll
        for (int j = 0; j < 4; j++)
#pragma unroll
            for (int q = 0; q < 4; q++) acc[i][j][q] = 0.f;

    const int row_l = tid >> 3, c4_l = tid & 7;

    auto issue = [&](int kt) {
        const int k0 = kt << 5;
        const uint32_t aB = sbase + (kt % 3) * STAGE_BYTES;
        const uint32_t bB = aB + 16384;
#pragma unroll
        for (int p = 0; p < 4; p++) {
            const int row = row_l + p * 32;
            const uint32_t so = SOFF(row, c4_l) * 4;
            CPA(aB + so, Ab + (size_t)(m0 + row) * K + k0 + c4_l * 4);
            CPA(bB + so, Bt + (size_t)(n0 + row) * ldb + kboff + k0 + c4_l * 4);
        }
        CPC();
    };

    auto compute = [&](int stg) {
        const uint32_t aB = sbase + stg * STAGE_BYTES;
        const uint32_t bB = aB + 16384;
        const int mA = lane & 15, cA = lane >> 4;
        const int nB = (lane & 7) + ((lane >> 4) << 3), cB = (lane >> 3) & 1;
#pragma unroll
        for (int kk = 0; kk < 4; kk++) {
            uint32_t fa[4][4], fb[2][4];
#pragma unroll
            for (int mf = 0; mf < 4; mf++) {
                const int m = wm + mf * 16 + mA;
                ldsm4(fa[mf], aB + SOFF(m, kk * 2 + cA) * 4);
            }
#pragma unroll
            for (int nfp = 0; nfp < 2; nfp++) {
                const int n = wn + nfp * 16 + nB;
                ldsm4(fb[nfp], bB + SOFF(n, kk * 2 + cB) * 4);
            }
#pragma unroll
            for (int mf = 0; mf < 4; mf++)
#pragma unroll
                for (int nf = 0; nf < 4; nf++)
                    mma8u(acc[mf][nf], fa[mf], fb[nf >> 1][(nf & 1) * 2],
                          fb[nf >> 1][(nf & 1) * 2 + 1]);
        }
    };

    const int nkt = K >> 5;
    issue(0);
    issue(1);
    for (int kt = 0; kt < nkt; kt++) {
        if (kt < nkt - 1) { CPW(1); } else { CPW(0); }
        __syncthreads();
        if (kt + 2 < nkt) issue(kt + 2);
        compute(kt % 3);
    }

    // ---- epilogue ----
#pragma unroll
    for (int mf = 0; mf < 4; mf++) {
#pragma unroll
        for (int rr = 0; rr < 2; rr++) {
            const int r = m0 + wm + mf * 16 + (lane >> 2) + rr * 8;
            float rzv = 1.f, actv = 1.f;
            if (BATCHED) rzv = rzb[r];
            if (EPI == 4) actv = act[r];
            float sE = 0.f, sD = 0.f;   // EPI 0 fused e-dots
#pragma unroll
            for (int nf = 0; nf < 4; nf++) {
                const int cc = n0 + wn + nf * 8 + (lane & 3) * 2;
                float v0 = acc[mf][nf][rr * 2 + 0];
                float v1 = acc[mf][nf][rr * 2 + 1];
                if (EPI == 0) {
                    const float c0 = cvt_tf32f(v0), c1 = cvt_tf32f(v1);
                    C[(size_t)cc * MROWS + r]       = c0;
                    C[(size_t)(cc + 1) * MROWS + r] = c1;
                    sE += c0 * bias[cc] + c1 * bias[cc + 1];
                    sD += c0 * X[cc] + c1 * X[cc + 1];
                } else {
                    if (BATCHED) { v0 *= rzv; v1 *= rzv; }
                    v0 += bias[cc]; v1 += bias[cc + 1];
                    if (EPI == 1) {
                        v0 = cvt_tf32f(fmaxf(v0, 0.f));
                        v1 = cvt_tf32f(fmaxf(v1, 0.f));
                    } else if (EPI == 2) {
                        const float* xr = Xb + (size_t)r * N + cc;
                        v0 += xr[0]; v1 += xr[1];
                    } else if (EPI == 3) {
                        const float* xr = Xb + (size_t)r * N + cc;
                        v0 = xr[0] + fmaxf(v0, 0.f); v1 = xr[1] + fmaxf(v1, 0.f);
                    } else if (EPI == 4) {
                        const float* xr = Xb + (size_t)r * N + cc;
                        v0 = (xr[0] + fmaxf(v0, 0.f)) * actv;
                        v1 = (xr[1] + fmaxf(v1, 0.f)) * actv;
                    }
                    *reinterpret_cast<float2*>(Cb + (size_t)r * N + cc) = make_float2(v0, v1);
                    if (EPI == 2 || EPI == 3) {
                        *reinterpret_cast<float2*>(Crb + (size_t)r * N + cc) =
                            make_float2(cvt_tf32f(v0), cvt_tf32f(v1));
                    }
                }
            }
            if (EPI == 0) {
                sE += __shfl_xor_sync(0xFFFFFFFFu, sE, 1);
                sE += __shfl_xor_sync(0xFFFFFFFFu, sE, 2);
                sD += __shfl_xor_sync(0xFFFFFFFFu, sD, 1);
                sD += __shfl_xor_sync(0xFFFFFFFFu, sD, 2);
                if ((lane & 3) == 0) {
                    atomicAdd(Cr + r, sE);            // esrc
                    atomicAdd(Cr + MROWS + r, sD);    // edst
                }
            }
        }
    }
}

// ---------------------------------------------------------------------------
// 32x32 tiled transpose with tf32 rounding: out[C][R] = cvt(in[R][C]^T)
// ---------------------------------------------------------------------------
__global__ void transpose_kernel(const float* __restrict__ in, float* __restrict__ out,
                                 int R, int Cc)
{
    __shared__ float tile[32][33];
    int c0 = blockIdx.x * 32, r0 = blockIdx.y * 32;
    int x = threadIdx.x, y = threadIdx.y;
#pragma unroll
    for (int i = 0; i < 32; i += 8)
        tile[y + i][x] = in[(size_t)(r0 + y + i) * Cc + c0 + x];
    __syncthreads();
#pragma unroll
    for (int i = 0; i < 32; i += 8)
        out[(size_t)(c0 + y + i) * R + r0 + x] = cvt_tf32f(tile[x][y + i]);
}

// ---------------------------------------------------------------------------
// adjT: bit s of word (b,t,s/32) = (adj[b][s][t]!=0) | (s==t)
// ---------------------------------------------------------------------------
__global__ __launch_bounds__(1024) void adjT_kernel(const int* __restrict__ adj)
{
    __shared__ int sa[32][33];
    const int b = blockIdx.z, t0 = blockIdx.y * 32, s0 = blockIdx.x * 32;
    const int w = threadIdx.x >> 5, lane = threadIdx.x & 31;
    sa[w][lane] = adj[((size_t)b * NN + s0 + w) * NN + t0 + lane];
    __syncthreads();
    const int t = t0 + w;
    uint32_t word = __ballot_sync(0xFFFFFFFFu, sa[lane][w] != 0);
    if (lane == 0) {
        if ((t >> 5) == (s0 >> 5)) word |= 1u << (t & 31);
        g_adjT[((size_t)b * NN + t) * (NN / 32) + (s0 >> 5)] = word;
    }
}

// ---------------------------------------------------------------------------
// Weff = emb_W1 @ emb_W2 ; beff = emb_b1 @ emb_W2 + emb_b2
// ---------------------------------------------------------------------------
__global__ void prep_weff_kernel(const float* __restrict__ W1, const float* __restrict__ b1,
                                 const float* __restrict__ W2, const float* __restrict__ b2)
{
    int j = blockIdx.x * 256 + threadIdx.x;
    if (j >= HH) return;
    float acc[6] = {0.f, 0.f, 0.f, 0.f, 0.f, 0.f};
    float bacc = b2[j];
    for (int k = 0; k < HH; k++) {
        float w2 = W2[k * HH + j];
        bacc += b1[k] * w2;
#pragma unroll
        for (int i = 0; i < 6; i++) acc[i] += W1[i * HH + k] * w2;
    }
#pragma unroll
    for (int i = 0; i < 6; i++) g_Weff[i * HH + j] = acc[i];
    g_beff[j] = bacc;
}

// ---------------------------------------------------------------------------
// Feature construction + fused 6->512 embedding; writes x and xr = tf32(x)
// ---------------------------------------------------------------------------
__global__ void embed_kernel(const float* __restrict__ arr, const float* __restrict__ dep,
                             const float* __restrict__ hard,
                             const float* __restrict__ ts, const float* __restrict__ tt)
{
    int idx = blockIdx.x * 256 + threadIdx.x;
    int j = idx & (HH - 1);
    int row = idx >> 9;
    int b = row >> 11;
    float t = ts[b], T = tt[b];
    float ar = arr[row], de = dep[row];
    float f[6];
    f[0] = (t - ar) / (de - ar);
    f[1] = t / T;
    f[2] = fmodf(f[1], 2.f);
    f[3] = fmodf(f[1], 4.f);
    f[4] = fmodf(f[1], 7.f);
    f[5] = hard[row];
    float acc = g_beff[j];
#pragma unroll
    for (int i = 0; i < 6; i++) acc += f[i] * g_Weff[i * HH + j];
    g_x[idx] = acc;
    g_xr[idx] = cvt_tf32f(acc);
}

// ---------------------------------------------------------------------------
// Zero esrc/edst + reset per-batch smax (before each layer's gemm0)
// ---------------------------------------------------------------------------
__global__ void zero_ee_kernel()
{
    int i = blockIdx.x * 256 + threadIdx.x;
    g_ee[i] = 0.f;
    g_ee[i + 2 * MROWS - gridDim.x * 256] = 0.f;  // unused pattern guard (never hit: grid covers 2*MROWS)
}

__global__ void zero_ee2_kernel()
{
    int i = blockIdx.x * 256 + threadIdx.x;
    if (i < 2 * MROWS) g_ee[i] = 0.f;
    if (i < NB) g_smax_bits[i] = 0x007FFFFFu;  // enc(-inf)
}

// ---------------------------------------------------------------------------
// Per-batch max of esrc -> g_smax_bits (after gemm0's fused dots)
// ---------------------------------------------------------------------------
__global__ __launch_bounds__(256) void smax_kernel()
{
    const int i = blockIdx.x * 256 + threadIdx.x;
    float v = g_ee[i];
#pragma unroll
    for (int off = 16; off; off >>= 1)
        v = fmaxf(v, __shfl_xor_sync(0xFFFFFFFFu, v, off));
    __shared__ float red[8];
    const int w = threadIdx.x >> 5, l = threadIdx.x & 31;
    if (l == 0) red[w] = v;
    __syncthreads();
    if (threadIdx.x == 0) {
        float m = red[0];
#pragma unroll
        for (int q = 1; q < 8; q++) m = fmaxf(m, red[q]);
        atomicMax(&g_smax_bits[i >> 11], enc_ord(m));
    }
}

// ---------------------------------------------------------------------------
// Per-node exp factors (all exponents <= 0 -> no overflow)
// ---------------------------------------------------------------------------
__global__ void nodeprep_kernel()
{
    int t = blockIdx.x * 256 + threadIdx.x;
    int b = t >> 11;
    float sm = dec_ord(g_smax_bits[b]);
    float es = g_ee[t], ed = g_ee[MROWS + t];
    g_f1[t] = __expf(es - sm);
    g_f2[t] = __expf(0.2f * (es - sm));
    float u = ed + sm;
    float mh = fmaxf(u, 0.2f * u);
    g_qa[t] = __expf(u - mh);
    g_qb[t] = __expf(0.2f * u - mh);
}

// ---------------------------------------------------------------------------
// Materialize P' (tf32-rounded) + fused row-sum -> g_rz. One warp per row.
// ---------------------------------------------------------------------------
__global__ __launch_bounds__(256) void pgen_kernel()
{
    const int wid = threadIdx.x >> 5, lane = threadIdx.x & 31;
    const int t = blockIdx.x * 8 + wid;
    const int b = t >> 11;
    const float qa = g_qa[t], qb = g_qb[t];
    const uint32_t* wrow = g_adjT + (size_t)t * (NN / 32);
    const float* f1 = g_f1 + b * NN;
    const float* f2 = g_f2 + b * NN;
    float* Prow = g_P + (size_t)t * NN;
    float sum = 0.f;
#pragma unroll 4
    for (int i = 0; i < 16; i++) {
        const int s = i * 128 + lane * 4;
        const uint32_t w = wrow[s >> 5];
        const uint32_t sh = s & 31;
        float4 x1 = *reinterpret_cast<const float4*>(f1 + s);
        float4 x2 = *reinterpret_cast<const float4*>(f2 + s);
        float4 o;
        o.x = ((w >> (sh + 0)) & 1u) ? cvt_tf32f(fmaxf(qa * x1.x, qb * x2.x)) : 0.f;
        o.y = ((w >> (sh + 1)) & 1u) ? cvt_tf32f(fmaxf(qa * x1.y, qb * x2.y)) : 0.f;
        o.z = ((w >> (sh + 2)) & 1u) ? cvt_tf32f(fmaxf(qa * x1.z, qb * x2.z)) : 0.f;
        o.w = ((w >> (sh + 3)) & 1u) ? cvt_tf32f(fmaxf(qa * x1.w, qb * x2.w)) : 0.f;
        sum += (o.x + o.y) + (o.z + o.w);
        *reinterpret_cast<float4*>(Prow + s) = o;
    }
#pragma unroll
    for (int off = 16; off; off >>= 1) sum += __shfl_xor_sync(0xFFFFFFFFu, sum, off);
    if (lane == 0) g_rz[t] = 1.f / fmaxf(sum, 1e-30f);
}

// ---------------------------------------------------------------------------
// Host launcher
// ---------------------------------------------------------------------------
extern "C" void kernel_launch(void* const* d_in, const int* in_sizes, int n_in,
                              void* d_out, int out_size)
{
    const int*   adj      = (const int*)d_in[0];
    const float* arrivals = (const float*)d_in[1];
    const float* depart   = (const float*)d_in[2];
    const float* hard     = (const float*)d_in[3];
    const float* active   = (const float*)d_in[4];
    const float* timestep = (const float*)d_in[5];
    const float* totalts  = (const float*)d_in[6];
    const float* embW1 = (const float*)d_in[7];
    const float* embb1 = (const float*)d_in[8];
    const float* embW2 = (const float*)d_in[9];
    const float* embb2 = (const float*)d_in[10];
    const float* gatW[3]    = {(const float*)d_in[11], (const float*)d_in[15], (const float*)d_in[19]};
    const float* gatAsrc[3] = {(const float*)d_in[12], (const float*)d_in[16], (const float*)d_in[20]};
    const float* gatAdst[3] = {(const float*)d_in[13], (const float*)d_in[17], (const float*)d_in[21]};
    const float* gatB[3]    = {(const float*)d_in[14], (const float*)d_in[18], (const float*)d_in[22]};
    const float* ffW1 = (const float*)d_in[23];
    const float* ffb1 = (const float*)d_in[24];
    const float* ffW2 = (const float*)d_in[25];
    const float* ffb2 = (const float*)d_in[26];

    float *x, *xr, *h, *hr, *hwt, *P, *rz, *wt, *ee;
    cudaGetSymbolAddress((void**)&x,   g_x);
    cudaGetSymbolAddress((void**)&xr,  g_xr);
    cudaGetSymbolAddress((void**)&h,   g_h);
    cudaGetSymbolAddress((void**)&hr,  g_hr);
    cudaGetSymbolAddress((void**)&hwt, g_hwt);
    cudaGetSymbolAddress((void**)&P,   g_P);
    cudaGetSymbolAddress((void**)&rz,  g_rz);
    cudaGetSymbolAddress((void**)&wt,  g_wt);
    cudaGetSymbolAddress((void**)&ee,  g_ee);

    static int smem_set = 0;
    if (!smem_set) {
        cudaFuncSetAttribute(gemm_tc<0>, cudaFuncAttributeMaxDynamicSharedMemorySize, SMEM_BYTES);
        cudaFuncSetAttribute(gemm_tc<1>, cudaFuncAttributeMaxDynamicSharedMemorySize, SMEM_BYTES);
        cudaFuncSetAttribute(gemm_tc<2>, cudaFuncAttributeMaxDynamicSharedMemorySize, SMEM_BYTES);
        cudaFuncSetAttribute(gemm_tc<3>, cudaFuncAttributeMaxDynamicSharedMemorySize, SMEM_BYTES);
        cudaFuncSetAttribute(gemm_tc<4>, cudaFuncAttributeMaxDynamicSharedMemorySize, SMEM_BYTES);
        smem_set = 1;
    }

    prep_weff_kernel<<<2, 256>>>(embW1, embb1, embW2, embb2);
    embed_kernel<<<(MROWS * HH) / 256, 256>>>(arrivals, depart, hard, timestep, totalts);
    adjT_kernel<<<dim3(NN / 32, NN / 32, NB), 1024>>>(adj);

    const int Kin[3] = {HH, 1024, 1024};
    const int Fo[3]  = {1024, 1024, HH};
    const dim3 tblk(32, 8);

    for (int l = 0; l < 3; l++) {
        const float* Ain = (l == 0) ? xr : hr;   // pre-rounded activations
        // wt = tf32(W^T) [Fo][Kin]
        transpose_kernel<<<dim3(Fo[l] / 32, Kin[l] / 32), tblk>>>(gatW[l], wt, Kin[l], Fo[l]);
        // zero e-accumulators + smax
        zero_ee2_kernel<<<(2 * MROWS) / 256, 256>>>();
        // hwt = (hin @ W)^T with fused esrc/edst partial dots
        gemm_tc<0><<<dim3(Fo[l] / 128, MROWS / 128), 256, SMEM_BYTES>>>(
            Ain, wt, hwt, ee, Kin[l], Fo[l], gatAsrc[l], gatAdst[l], nullptr, nullptr);
        smax_kernel<<<MROWS / 256, 256>>>();
        nodeprep_kernel<<<MROWS / 256, 256>>>();
        pgen_kernel<<<MROWS / 8, 256>>>();
        if (l < 2) {
            // tf32-only activation store (fp32 copy is never read for l<2)
            gemm_tc<1><<<dim3(Fo[l] / 128, NN / 128, NB), 256, SMEM_BYTES>>>(
                P, hwt, hr, nullptr, NN, Fo[l], gatB[l], nullptr, nullptr, rz);
        } else {
            gemm_tc<2><<<dim3(Fo[l] / 128, NN / 128, NB), 256, SMEM_BYTES>>>(
                P, hwt, h, hr, NN, Fo[l], gatB[l], x, nullptr, rz);
        }
    }

    // ff1: x2 = x1 + relu(x1 @ W1 + b1)   (A = hr pre-rounded, X = h fp32)
    transpose_kernel<<<dim3(HH / 32, HH / 32), tblk>>>(ffW1, wt, HH, HH);
    gemm_tc<3><<<dim3(HH / 128, MROWS / 128), 256, SMEM_BYTES>>>(
        hr, wt, x, xr, HH, HH, ffb1, h, nullptr, nullptr);
    // ff2: out = (x2 + relu(x2 @ W2 + b2)) * active   (A = xr)
    transpose_kernel<<<dim3(HH / 32, HH / 32), tblk>>>(ffW2, wt, HH, HH);
    gemm_tc<4><<<dim3(HH / 128, MROWS / 128), 256, SMEM_BYTES>>>(
        xr, wt, (float*)d_out, nullptr, HH, HH, ffb2, x, active, nullptr);
}

// round 10
// speedup vs baseline: 1.9102x; 1.5318x over previous
#include <cuda_runtime.h>
#include <cuda_fp16.h>
#include <cstdint>

#define NB 8
#define NN 2048
#define HH 512
#define MROWS (NB * NN)   // 16384

// ---------------------------------------------------------------------------
// Scratch (device globals — no allocation allowed)
// ---------------------------------------------------------------------------
__device__ float  g_x[MROWS * HH];                 // residual x (fp32)
__device__ __half g_xr[MROWS * HH];                // fp16 copy of x
__device__ float  g_h[MROWS * 1024];               // fp32 activations (layer-2 only)
__device__ __half g_hr[MROWS * 1024];              // fp16 activations
__device__ __half g_hwt[(size_t)1024 * MROWS];     // (h @ W)^T [Fo][MROWS], fp16
__device__ __half g_P[(size_t)MROWS * NN];         // unnormalized attention, fp16
__device__ __half g_wt[1024 * 1024];               // W^T [N][K], fp16
__device__ uint32_t g_adjT[MROWS * (NN / 32)];     // bit: valid(t, s), self-loop folded
__device__ float  g_ee[2 * MROWS];                 // [0..M) esrc, [M..2M) edst
__device__ float  g_f1[MROWS], g_f2[MROWS];        // per-source exp factors
__device__ float  g_qa[MROWS], g_qb[MROWS];        // per-target exp factors
__device__ float  g_rz[MROWS];                     // 1 / row-sum of P'
__device__ unsigned int g_smax_bits[NB];           // orderable-int max of esrc per batch
__device__ float  g_Weff[6 * HH];
__device__ float  g_beff[HH];

// ---------------------------------------------------------------------------
// Helpers
// ---------------------------------------------------------------------------
__device__ __forceinline__ unsigned enc_ord(float f) {
    unsigned i = __float_as_uint(f);
    return (i & 0x80000000u) ? ~i : (i | 0x80000000u);
}
__device__ __forceinline__ float dec_ord(unsigned k) {
    unsigned i = (k & 0x80000000u) ? (k & 0x7FFFFFFFu) : ~k;
    return __uint_as_float(i);
}
__device__ __forceinline__ uint32_t smem_u32(const void* p) {
    uint32_t a;
    asm("{ .reg .u64 t; cvta.to.shared.u64 t, %1; cvt.u32.u64 %0, t; }" : "=r"(a) : "l"(p));
    return a;
}
// fp16 MMA m16n8k16: A 4 regs, B 2 regs, C 4 f32
__device__ __forceinline__ void mma16(float* c, const uint32_t* a, const uint32_t* b) {
    asm volatile(
        "mma.sync.aligned.m16n8k16.row.col.f32.f16.f16.f32 "
        "{%0,%1,%2,%3}, {%4,%5,%6,%7}, {%8,%9}, {%0,%1,%2,%3};"
        : "+f"(c[0]), "+f"(c[1]), "+f"(c[2]), "+f"(c[3])
        : "r"(a[0]), "r"(a[1]), "r"(a[2]), "r"(a[3]), "r"(b[0]), "r"(b[1]));
}
__device__ __forceinline__ void ldsm4(uint32_t* r, uint32_t addr) {
    asm volatile("ldmatrix.sync.aligned.m8n8.x4.shared.b16 {%0,%1,%2,%3}, [%4];"
                 : "=r"(r[0]), "=r"(r[1]), "=r"(r[2]), "=r"(r[3]) : "r"(addr));
}
#define CPA(dst, src) asm volatile("cp.async.cg.shared.global [%0], [%1], 16;" :: "r"(dst), "l"(src))
#define CPC() asm volatile("cp.async.commit_group;")
#define CPW(n) asm volatile("cp.async.wait_group %0;" :: "n"(n))

// k-major fp16 tile: 128 rows x 64 halfs (128 bytes/row). 16B chunk c4k = 0..7.
// byte offset of chunk (row, c4k): row*128 + ((c4k ^ (row&7)) << 4)
#define SOFFB(row, c4k) ((row) * 128 + ((((c4k)) ^ ((row) & 7)) << 4))

#define STAGE_BYTES 32768                 // A 16KB + B 16KB per stage (kt = 64)
#define SMEM_BYTES (3 * STAGE_BYTES)      // 96 KB, 2 CTAs/SM

// ---------------------------------------------------------------------------
// Unified fp16 tensor-core GEMM (fp32 accumulate). All operands fp16 in gmem.
// C[M,N] = A[M,K] @ Bt^T.  A row-major [M][K], Bt [N][K], k-contiguous.
// CTA tile 128x128, 8 warps (2m x 4n), warp tile 64x32, kt=64, 3-stage cp.async.
// EPI 0: Ch^T[n][m] = h(acc); fused esrc/edst dots (bias=asrc, X=adst, ee)
// EPI 1: Ch = h(relu(acc*rz + bias))               (attention mid, batched)
// EPI 2: C = acc*rz + bias + X; Ch = h(C)          (attention last, batched)
// EPI 3: C = X + relu(acc + bias); Ch = h(C)       (ff1)
// EPI 4: C = (X + relu(acc + bias)) * act[row]     (ff2, final fp32 output)
// ---------------------------------------------------------------------------
template <int EPI>
__global__ __launch_bounds__(256, 2) void gemm_tc(
    const __half* __restrict__ A, const __half* __restrict__ Bt,
    float* __restrict__ C, __half* __restrict__ Ch, int K, int N,
    const float* __restrict__ bias, const float* __restrict__ X,
    const float* __restrict__ act, const float* __restrict__ rz,
    float* __restrict__ ee)
{
    constexpr bool BATCHED = (EPI == 1 || EPI == 2);
    extern __shared__ char smc[];
    const uint32_t sbase = smem_u32(smc);
    const int tid = threadIdx.x;
    const int lane = tid & 31, wid = tid >> 5;

    // CTA rasterization swizzle: groups of 4 m-rows x full n share L2
    int bx = blockIdx.x, by = blockIdx.y;
    {
        const int GX = gridDim.x;
        const int lin = by * GX + bx;
        const int grp = lin / (4 * GX);
        const int rem = lin - grp * 4 * GX;
        by = grp * 4 + (rem & 3);
        bx = rem >> 2;
    }
    const int m0 = by * 128, n0 = bx * 128;
    const int ws = wid >> 2, wcs = wid & 3;
    const int wm = ws * 64, wn = wcs * 32;

    int zoff = 0;
    if (BATCHED) zoff = blockIdx.z * NN;
    const __half* Ab = A + (size_t)zoff * K;
    const int ldb = BATCHED ? MROWS : K;
    const int kboff = BATCHED ? zoff : 0;
    float* Cb = (C != nullptr) ? C + (size_t)zoff * N : nullptr;
    __half* Chb = (Ch != nullptr && EPI != 0) ? Ch + (size_t)zoff * N : Ch;
    const float* Xb = (EPI >= 2) ? X + (size_t)zoff * N : nullptr;
    const float* rzb = BATCHED ? rz + zoff : nullptr;

    float acc[4][4][4];
#pragma unroll
    for (int i = 0; i < 4; i++)
#pragma unroll
        for (int j = 0; j < 4; j++)
#pragma unroll
            for (int q = 0; q < 4; q++) acc[i][j][q] = 0.f;

    const int row_l = tid >> 3, c4_l = tid & 7;   // staging slot

    auto issue = [&](int kt) {
        const int k0 = kt << 6;                    // 64 halfs per tile
        const uint32_t aB = sbase + (kt % 3) * STAGE_BYTES;
        const uint32_t bB = aB + 16384;
#pragma unroll
        for (int p = 0; p < 4; p++) {
            const int row = row_l + p * 32;
            const uint32_t so = SOFFB(row, c4_l);
            CPA(aB + so, Ab + (size_t)(m0 + row) * K + k0 + c4_l * 8);
            CPA(bB + so, Bt + (size_t)(n0 + row) * ldb + kboff + k0 + c4_l * 8);
        }
        CPC();
    };

    // ldsm lane mappings
    const int mA_row = lane & 15, mA_k = lane >> 4;                 // A 16x16
    const int nB_row = (lane & 7) + ((lane >> 4) << 3);             // B 16x16 (two n-groups)
    const int nB_k = (lane >> 3) & 1;

    auto compute = [&](int stg) {
        const uint32_t aB = sbase + stg * STAGE_BYTES;
        const uint32_t bB = aB + 16384;
#pragma unroll
        for (int kk = 0; kk < 4; kk++) {          // four k16 steps per tile
            uint32_t fa[4][4], fb[2][4];
#pragma unroll
            for (int mf = 0; mf < 4; mf++)
                ldsm4(fa[mf], aB + SOFFB(wm + mf * 16 + mA_row, kk * 2 + mA_k));
#pragma unroll
            for (int bp = 0; bp < 2; bp++)
                ldsm4(fb[bp], bB + SOFFB(wn + bp * 16 + nB_row, kk * 2 + nB_k));
#pragma unroll
            for (int mf = 0; mf < 4; mf++)
#pragma unroll
                for (int nf = 0; nf < 4; nf++)
                    mma16(acc[mf][nf], fa[mf], &fb[nf >> 1][(nf & 1) * 2]);
        }
    };

    const int nkt = K >> 6;
    issue(0);
    issue(1);
    for (int kt = 0; kt < nkt; kt++) {
        if (kt < nkt - 1) { CPW(1); } else { CPW(0); }
        __syncthreads();
        if (kt + 2 < nkt) issue(kt + 2);
        compute(kt % 3);
    }

    // ---- epilogue ----
#pragma unroll
    for (int mf = 0; mf < 4; mf++) {
#pragma unroll
        for (int rr = 0; rr < 2; rr++) {
            const int r = m0 + wm + mf * 16 + (lane >> 2) + rr * 8;
            float rzv = 1.f, actv = 1.f;
            if (BATCHED) rzv = rzb[r];
            if (EPI == 4) actv = act[r];
            float sE = 0.f, sD = 0.f;
#pragma unroll
            for (int nf = 0; nf < 4; nf++) {
                const int cc = n0 + wn + nf * 8 + (lane & 3) * 2;
                float v0 = acc[mf][nf][rr * 2 + 0];
                float v1 = acc[mf][nf][rr * 2 + 1];
                if (EPI == 0) {
                    const __half h0 = __float2half_rn(v0);
                    const __half h1 = __float2half_rn(v1);
                    Ch[(size_t)cc * MROWS + r]       = h0;
                    Ch[(size_t)(cc + 1) * MROWS + r] = h1;
                    const float c0 = __half2float(h0), c1 = __half2float(h1);
                    sE += c0 * bias[cc] + c1 * bias[cc + 1];
                    sD += c0 * X[cc] + c1 * X[cc + 1];
                } else {
                    if (BATCHED) { v0 *= rzv; v1 *= rzv; }
                    v0 += bias[cc]; v1 += bias[cc + 1];
                    if (EPI == 1) {
                        v0 = fmaxf(v0, 0.f); v1 = fmaxf(v1, 0.f);
                        *reinterpret_cast<__half2*>(Chb + (size_t)r * N + cc) =
                            __floats2half2_rn(v0, v1);
                    } else {
                        if (EPI == 2) {
                            const float* xr = Xb + (size_t)r * N + cc;
                            v0 += xr[0]; v1 += xr[1];
                        } else if (EPI == 3) {
                            const float* xr = Xb + (size_t)r * N + cc;
                            v0 = xr[0] + fmaxf(v0, 0.f); v1 = xr[1] + fmaxf(v1, 0.f);
                        } else if (EPI == 4) {
                            const float* xr = Xb + (size_t)r * N + cc;
                            v0 = (xr[0] + fmaxf(v0, 0.f)) * actv;
                            v1 = (xr[1] + fmaxf(v1, 0.f)) * actv;
                        }
                        *reinterpret_cast<float2*>(Cb + (size_t)r * N + cc) = make_float2(v0, v1);
                        if (EPI == 2 || EPI == 3) {
                            *reinterpret_cast<__half2*>(Chb + (size_t)r * N + cc) =
                                __floats2half2_rn(v0, v1);
                        }
                    }
                }
            }
            if (EPI == 0) {
                sE += __shfl_xor_sync(0xFFFFFFFFu, sE, 1);
                sE += __shfl_xor_sync(0xFFFFFFFFu, sE, 2);
                sD += __shfl_xor_sync(0xFFFFFFFFu, sD, 1);
                sD += __shfl_xor_sync(0xFFFFFFFFu, sD, 2);
                if ((lane & 3) == 0) {
                    atomicAdd(ee + r, sE);
                    atomicAdd(ee + MROWS + r, sD);
                }
            }
        }
    }
}

// ---------------------------------------------------------------------------
// 32x32 tiled transpose to fp16: out[C][R] = h(in[R][C]^T)
// ---------------------------------------------------------------------------
__global__ void transpose_kernel(const float* __restrict__ in, __half* __restrict__ out,
                                 int R, int Cc)
{
    __shared__ float tile[32][33];
    int c0 = blockIdx.x * 32, r0 = blockIdx.y * 32;
    int x = threadIdx.x, y = threadIdx.y;
#pragma unroll
    for (int i = 0; i < 32; i += 8)
        tile[y + i][x] = in[(size_t)(r0 + y + i) * Cc + c0 + x];
    __syncthreads();
#pragma unroll
    for (int i = 0; i < 32; i += 8)
        out[(size_t)(c0 + y + i) * R + r0 + x] = __float2half_rn(tile[x][y + i]);
}

// ---------------------------------------------------------------------------
// adjT: bit s of word (b,t,s/32) = (adj[b][s][t]!=0) | (s==t)
// ---------------------------------------------------------------------------
__global__ __launch_bounds__(1024) void adjT_kernel(const int* __restrict__ adj)
{
    __shared__ int sa[32][33];
    const int b = blockIdx.z, t0 = blockIdx.y * 32, s0 = blockIdx.x * 32;
    const int w = threadIdx.x >> 5, lane = threadIdx.x & 31;
    sa[w][lane] = adj[((size_t)b * NN + s0 + w) * NN + t0 + lane];
    __syncthreads();
    const int t = t0 + w;
    uint32_t word = __ballot_sync(0xFFFFFFFFu, sa[lane][w] != 0);
    if (lane == 0) {
        if ((t >> 5) == (s0 >> 5)) word |= 1u << (t & 31);
        g_adjT[((size_t)b * NN + t) * (NN / 32) + (s0 >> 5)] = word;
    }
}

// ---------------------------------------------------------------------------
// Weff = emb_W1 @ emb_W2 ; beff = emb_b1 @ emb_W2 + emb_b2
// ---------------------------------------------------------------------------
__global__ void prep_weff_kernel(const float* __restrict__ W1, const float* __restrict__ b1,
                                 const float* __restrict__ W2, const float* __restrict__ b2)
{
    int j = blockIdx.x * 256 + threadIdx.x;
    if (j >= HH) return;
    float acc[6] = {0.f, 0.f, 0.f, 0.f, 0.f, 0.f};
    float bacc = b2[j];
    for (int k = 0; k < HH; k++) {
        float w2 = W2[k * HH + j];
        bacc += b1[k] * w2;
#pragma unroll
        for (int i = 0; i < 6; i++) acc[i] += W1[i * HH + k] * w2;
    }
#pragma unroll
    for (int i = 0; i < 6; i++) g_Weff[i * HH + j] = acc[i];
    g_beff[j] = bacc;
}

// ---------------------------------------------------------------------------
// Feature construction + fused 6->512 embedding; writes x (fp32) and xr (fp16)
// ---------------------------------------------------------------------------
__global__ void embed_kernel(const float* __restrict__ arr, const float* __restrict__ dep,
                             const float* __restrict__ hard,
                             const float* __restrict__ ts, const float* __restrict__ tt)
{
    int idx = blockIdx.x * 256 + threadIdx.x;
    int j = idx & (HH - 1);
    int row = idx >> 9;
    int b = row >> 11;
    float t = ts[b], T = tt[b];
    float ar = arr[row], de = dep[row];
    float f[6];
    f[0] = (t - ar) / (de - ar);
    f[1] = t / T;
    f[2] = fmodf(f[1], 2.f);
    f[3] = fmodf(f[1], 4.f);
    f[4] = fmodf(f[1], 7.f);
    f[5] = hard[row];
    float acc = g_beff[j];
#pragma unroll
    for (int i = 0; i < 6; i++) acc += f[i] * g_Weff[i * HH + j];
    g_x[idx] = acc;
    g_xr[idx] = __float2half_rn(acc);
}

// ---------------------------------------------------------------------------
// Zero e-accumulators + reset per-batch smax (before each layer's gemm0)
// ---------------------------------------------------------------------------
__global__ void zero_ee2_kernel()
{
    int i = blockIdx.x * 256 + threadIdx.x;
    if (i < 2 * MROWS) g_ee[i] = 0.f;
    if (i < NB) g_smax_bits[i] = 0x007FFFFFu;  // enc(-inf)
}

// ---------------------------------------------------------------------------
// Per-batch max of esrc -> g_smax_bits
// ---------------------------------------------------------------------------
__global__ __launch_bounds__(256) void smax_kernel()
{
    const int i = blockIdx.x * 256 + threadIdx.x;
    float v = g_ee[i];
#pragma unroll
    for (int off = 16; off; off >>= 1)
        v = fmaxf(v, __shfl_xor_sync(0xFFFFFFFFu, v, off));
    __shared__ float red[8];
    const int w = threadIdx.x >> 5, l = threadIdx.x & 31;
    if (l == 0) red[w] = v;
    __syncthreads();
    if (threadIdx.x == 0) {
        float m = red[0];
#pragma unroll
        for (int q = 1; q < 8; q++) m = fmaxf(m, red[q]);
        atomicMax(&g_smax_bits[i >> 11], enc_ord(m));
    }
}

// ---------------------------------------------------------------------------
// Per-node exp factors (all exponents <= 0 -> no overflow)
// ---------------------------------------------------------------------------
__global__ void nodeprep_kernel()
{
    int t = blockIdx.x * 256 + threadIdx.x;
    int b = t >> 11;
    float sm = dec_ord(g_smax_bits[b]);
    float es = g_ee[t], ed = g_ee[MROWS + t];
    g_f1[t] = __expf(es - sm);
    g_f2[t] = __expf(0.2f * (es - sm));
    float u = ed + sm;
    float mh = fmaxf(u, 0.2f * u);
    g_qa[t] = __expf(u - mh);
    g_qb[t] = __expf(0.2f * u - mh);
}

// ---------------------------------------------------------------------------
// Materialize P' (fp16) + fused row-sum of the fp16-rounded values -> g_rz.
// One warp per target row.
// ---------------------------------------------------------------------------
__global__ __launch_bounds__(256) void pgen_kernel()
{
    const int wid = threadIdx.x >> 5, lane = threadIdx.x & 31;
    const int t = blockIdx.x * 8 + wid;
    const int b = t >> 11;
    const float qa = g_qa[t], qb = g_qb[t];
    const uint32_t* wrow = g_adjT + (size_t)t * (NN / 32);
    const float* f1 = g_f1 + b * NN;
    const float* f2 = g_f2 + b * NN;
    __half* Prow = g_P + (size_t)t * NN;
    float sum = 0.f;
#pragma unroll 4
    for (int i = 0; i < 16; i++) {
        const int s = i * 128 + lane * 4;
        const uint32_t w = wrow[s >> 5];
        const uint32_t sh = s & 31;
        float4 x1 = *reinterpret_cast<const float4*>(f1 + s);
        float4 x2 = *reinterpret_cast<const float4*>(f2 + s);
        float o0 = ((w >> (sh + 0)) & 1u) ? fmaxf(qa * x1.x, qb * x2.x) : 0.f;
        float o1 = ((w >> (sh + 1)) & 1u) ? fmaxf(qa * x1.y, qb * x2.y) : 0.f;
        float o2 = ((w >> (sh + 2)) & 1u) ? fmaxf(qa * x1.z, qb * x2.z) : 0.f;
        float o3 = ((w >> (sh + 3)) & 1u) ? fmaxf(qa * x1.w, qb * x2.w) : 0.f;
        __half2 p01 = __floats2half2_rn(o0, o1);
        __half2 p23 = __floats2half2_rn(o2, o3);
        float2 q01 = __half22float2(p01);
        float2 q23 = __half22float2(p23);
        sum += (q01.x + q01.y) + (q23.x + q23.y);
        *reinterpret_cast<__half2*>(Prow + s)     = p01;
        *reinterpret_cast<__half2*>(Prow + s + 2) = p23;
    }
#pragma unroll
    for (int off = 16; off; off >>= 1) sum += __shfl_xor_sync(0xFFFFFFFFu, sum, off);
    if (lane == 0) g_rz[t] = 1.f / fmaxf(sum, 1e-30f);
}

// ---------------------------------------------------------------------------
// Host launcher
// ---------------------------------------------------------------------------
extern "C" void kernel_launch(void* const* d_in, const int* in_sizes, int n_in,
                              void* d_out, int out_size)
{
    const int*   adj      = (const int*)d_in[0];
    const float* arrivals = (const float*)d_in[1];
    const float* depart   = (const float*)d_in[2];
    const float* hard     = (const float*)d_in[3];
    const float* active   = (const float*)d_in[4];
    const float* timestep = (const float*)d_in[5];
    const float* totalts  = (const float*)d_in[6];
    const float* embW1 = (const float*)d_in[7];
    const float* embb1 = (const float*)d_in[8];
    const float* embW2 = (const float*)d_in[9];
    const float* embb2 = (const float*)d_in[10];
    const float* gatW[3]    = {(const float*)d_in[11], (const float*)d_in[15], (const float*)d_in[19]};
    const float* gatAsrc[3] = {(const float*)d_in[12], (const float*)d_in[16], (const float*)d_in[20]};
    const float* gatAdst[3] = {(const float*)d_in[13], (const float*)d_in[17], (const float*)d_in[21]};
    const float* gatB[3]    = {(const float*)d_in[14], (const float*)d_in[18], (const float*)d_in[22]};
    const float* ffW1 = (const float*)d_in[23];
    const float* ffb1 = (const float*)d_in[24];
    const float* ffW2 = (const float*)d_in[25];
    const float* ffb2 = (const float*)d_in[26];

    float *x, *h, *rz, *ee;
    __half *xr, *hr, *hwt, *P, *wt;
    cudaGetSymbolAddress((void**)&x,   g_x);
    cudaGetSymbolAddress((void**)&xr,  g_xr);
    cudaGetSymbolAddress((void**)&h,   g_h);
    cudaGetSymbolAddress((void**)&hr,  g_hr);
    cudaGetSymbolAddress((void**)&hwt, g_hwt);
    cudaGetSymbolAddress((void**)&P,   g_P);
    cudaGetSymbolAddress((void**)&rz,  g_rz);
    cudaGetSymbolAddress((void**)&wt,  g_wt);
    cudaGetSymbolAddress((void**)&ee,  g_ee);

    static int smem_set = 0;
    if (!smem_set) {
        cudaFuncSetAttribute(gemm_tc<0>, cudaFuncAttributeMaxDynamicSharedMemorySize, SMEM_BYTES);
        cudaFuncSetAttribute(gemm_tc<1>, cudaFuncAttributeMaxDynamicSharedMemorySize, SMEM_BYTES);
        cudaFuncSetAttribute(gemm_tc<2>, cudaFuncAttributeMaxDynamicSharedMemorySize, SMEM_BYTES);
        cudaFuncSetAttribute(gemm_tc<3>, cudaFuncAttributeMaxDynamicSharedMemorySize, SMEM_BYTES);
        cudaFuncSetAttribute(gemm_tc<4>, cudaFuncAttributeMaxDynamicSharedMemorySize, SMEM_BYTES);
        smem_set = 1;
    }

    prep_weff_kernel<<<2, 256>>>(embW1, embb1, embW2, embb2);
    embed_kernel<<<(MROWS * HH) / 256, 256>>>(arrivals, depart, hard, timestep, totalts);
    adjT_kernel<<<dim3(NN / 32, NN / 32, NB), 1024>>>(adj);

    const int Kin[3] = {HH, 1024, 1024};
    const int Fo[3]  = {1024, 1024, HH};
    const dim3 tblk(32, 8);

    for (int l = 0; l < 3; l++) {
        const __half* Ain = (l == 0) ? xr : hr;
        // wt = h(W^T) [Fo][Kin]
        transpose_kernel<<<dim3(Fo[l] / 32, Kin[l] / 32), tblk>>>(gatW[l], wt, Kin[l], Fo[l]);
        zero_ee2_kernel<<<(2 * MROWS) / 256, 256>>>();
        // hwt = (hin @ W)^T (fp16, transposed) + fused esrc/edst dots
        gemm_tc<0><<<dim3(Fo[l] / 128, MROWS / 128), 256, SMEM_BYTES>>>(
            Ain, wt, nullptr, hwt, Kin[l], Fo[l], gatAsrc[l], gatAdst[l], nullptr, nullptr, ee);
        smax_kernel<<<MROWS / 256, 256>>>();
        nodeprep_kernel<<<MROWS / 256, 256>>>();
        pgen_kernel<<<MROWS / 8, 256>>>();
        if (l < 2) {
            gemm_tc<1><<<dim3(Fo[l] / 128, NN / 128, NB), 256, SMEM_BYTES>>>(
                P, hwt, nullptr, hr, NN, Fo[l], gatB[l], nullptr, nullptr, rz, nullptr);
        } else {
            gemm_tc<2><<<dim3(Fo[l] / 128, NN / 128, NB), 256, SMEM_BYTES>>>(
                P, hwt, h, hr, NN, Fo[l], gatB[l], x, nullptr, rz, nullptr);
        }
    }

    // ff1: x2 = x1 + relu(x1 @ W1 + b1)   (A = hr fp16, X = h fp32)
    transpose_kernel<<<dim3(HH / 32, HH / 32), tblk>>>(ffW1, wt, HH, HH);
    gemm_tc<3><<<dim3(HH / 128, MROWS / 128), 256, SMEM_BYTES>>>(
        hr, wt, x, xr, HH, HH, ffb1, h, nullptr, nullptr, nullptr);
    // ff2: out = (x2 + relu(x2 @ W2 + b2)) * active   (A = xr fp16)
    transpose_kernel<<<dim3(HH / 32, HH / 32), tblk>>>(ffW2, wt, HH, HH);
    gemm_tc<4><<<dim3(HH / 128, MROWS / 128), 256, SMEM_BYTES>>>(
        xr, wt, (float*)d_out, nullptr, HH, HH, ffb2, x, active, nullptr, nullptr);
}